// round 15
// baseline (speedup 1.0000x reference)
#include <cuda_runtime.h>

#define FULL 0xffffffffu
typedef unsigned int u32;

constexpr int L = 16;
constexpr int RING = 8;
constexpr float LOG2E = 1.4426950408889634f;
constexpr float LN2   = 0.6931471805599453f;

__device__ int g_perm[4096];

__device__ __forceinline__ float ex2f(float v) {
    float r; asm("ex2.approx.f32 %0,%1;" : "=f"(r) : "f"(v)); return r;
}
__device__ __forceinline__ u32 pkbf(float hi, float lo) {
    u32 r; asm("cvt.rn.bf16x2.f32 %0,%1,%2;" : "=r"(r) : "f"(hi), "f"(lo)); return r;
}
__device__ __forceinline__ u32 mulbf2(u32 a, u32 b) {
    u32 r; asm("mul.rn.bf16x2 %0,%1,%2;" : "=r"(r) : "r"(a), "r"(b)); return r;
}
__device__ __forceinline__ float bflo(u32 v) { return __uint_as_float(v << 16); }
__device__ __forceinline__ float bfhi(u32 v) { return __uint_as_float(v & 0xffff0000u); }

__device__ __forceinline__ void mma16816(
    float& d0, float& d1, float& d2, float& d3,
    u32 a0, u32 a1, u32 a2, u32 a3, u32 b0, u32 b1)
{
    asm volatile(
        "mma.sync.aligned.m16n8k16.row.col.f32.bf16.bf16.f32 "
        "{%0,%1,%2,%3}, {%4,%5,%6,%7}, {%8,%9}, {%10,%11,%12,%13};"
        : "=f"(d0), "=f"(d1), "=f"(d2), "=f"(d3)
        : "r"(a0), "r"(a1), "r"(a2), "r"(a3), "r"(b0), "r"(b1),
          "f"(0.f), "f"(0.f), "f"(0.f), "f"(0.f));
}

// state permutation on the MMA k/n axes
__host__ __device__ __forceinline__ int sigma(int i) {
    return (i < 8) ? ((i & 1) ? 2 * i - 1 : 2 * i)
                   : ((i & 1) ? 2 * i - 15 : 2 * i - 14);
}

// ---------- kernel 1: counting sort of batch indices by length ----------
__global__ void sort_kernel(const int* __restrict__ length, int B) {
    __shared__ int hist[513];
    __shared__ int offs[513];
    int tid = threadIdx.x;   // 512 threads
    for (int i = tid; i < 513; i += 512) hist[i] = 0;
    __syncthreads();
    for (int i = tid; i < B; i += 512) atomicAdd(&hist[length[i]], 1);
    __syncthreads();
    if (tid == 0) {
        int acc = 0;
        for (int v = 1; v <= 512; ++v) { offs[v] = acc; acc += hist[v]; }
    }
    __syncthreads();
    for (int i = tid; i < B; i += 512) {
        int pos = atomicAdd(&offs[length[i]], 1);
        g_perm[pos] = i;
    }
}

// ---------- kernel 2: R13 recursion over length-sorted groups ----------
// 512 sorted groups of 8 batches. Block bid owns groups
// {2bid, 2bid+1, 511-2bid, 510-2bid} (short pair + complementary long pair).
// 12 warps: w0-3 fwd of group-slot 0-3; w4-7 bwd of group-slot 2,3,0,1
// (so SMSP k gets fwd(len a) + bwd(len ~512-a) -> ~equal work everywhere);
// w8-11 emit of group-slot 0-3.
__global__ __launch_bounds__(384, 1) void crf_kernel(
    const float* __restrict__ x, const float* __restrict__ trans,
    const int* __restrict__ label, const int* __restrict__ length,
    float* __restrict__ out, int B, int T)
{
    __shared__ float sE[L * L];
    __shared__ float sT[L * L];
    __shared__ u32   sFA[4][32][2];   // fwd final (A0, A2) per lane, per group-slot
    __shared__ int   sMf[4][8];
    __shared__ float sScore[4][8];

    int tid  = threadIdx.x;
    int lane = tid & 31;
    int w    = tid >> 5;
    int g    = lane >> 2;     // batch row 0..7
    int tig  = lane & 3;

    if (tid < L * L) {
        float tv = trans[tid];
        sT[tid] = tv;
        sE[tid] = tv * LOG2E;
    }
    __syncthreads();

    int bid = blockIdx.x;
    int nG  = B / 8;   // 512
    int Gs[4] = {2 * bid, 2 * bid + 1, (nG - 1) - 2 * bid, (nG - 2) - 2 * bid};

    if (w < 8) {
        bool isBwd = w >= 4;
        int slot = isBwd ? (((w & 3) + 2) & 3) : (w & 3);
        int group = Gs[slot];
        int b = g_perm[group * 8 + g];
        int len = length[b];
        int m = (len - 1) >> 1;
        int cnt  = isBwd ? max(len - 2 - m, 0) : m;
        int base = isBwd ? (len - 2) : 1;
        int dir  = isBwd ? -1 : 1;
        int cl   = max(cnt - 1, 0);

        int kMax = cnt;
#pragma unroll
        for (int o = 4; o <= 16; o <<= 1)
            kMax = max(kMax, __shfl_xor_sync(FULL, kMax, o));
        int kMaxPad = (kMax + RING - 1) & ~(RING - 1);

        // B fragments with sigma on both axes:
        u32 b00, b01, b10, b11;
        {
            int r0 = 4 * tig;
            int cA = sigma(g);
            int cB = sigma(g + 8);
            float e00, e01, e02, e03, e10, e11, e12, e13;
            if (!isBwd) {
                e00 = sE[r0 * L + cA];       e01 = sE[(r0 + 1) * L + cA];
                e02 = sE[(r0 + 2) * L + cA]; e03 = sE[(r0 + 3) * L + cA];
                e10 = sE[r0 * L + cB];       e11 = sE[(r0 + 1) * L + cB];
                e12 = sE[(r0 + 2) * L + cB]; e13 = sE[(r0 + 3) * L + cB];
            } else {
                e00 = sE[cA * L + r0];       e01 = sE[cA * L + r0 + 1];
                e02 = sE[cA * L + r0 + 2];   e03 = sE[cA * L + r0 + 3];
                e10 = sE[cB * L + r0];       e11 = sE[cB * L + r0 + 1];
                e12 = sE[cB * L + r0 + 2];   e13 = sE[cB * L + r0 + 3];
            }
            b00 = pkbf(ex2f(e01), ex2f(e00));
            b01 = pkbf(ex2f(e03), ex2f(e02));
            b10 = pkbf(ex2f(e11), ex2f(e10));
            b11 = pkbf(ex2f(e13), ex2f(e12));
        }

        // thread tig owns states 4*tig..4*tig+3 of batch b (one float4 per row)
        const float* p = x + (size_t)b * T * L + tig * 4;

        // init: s = exp(x at row 0 (fwd) / len-1 (bwd))
        int ir = isBwd ? (len - 1) : 0;
        float4 iv = *(const float4*)(p + (size_t)ir * L);
        u32 A0 = pkbf(ex2f(iv.y * LOG2E), ex2f(iv.x * LOG2E));
        u32 A2 = pkbf(ex2f(iv.w * LOG2E), ex2f(iv.z * LOG2E));
        int Ms = 0;

        // RING-deep prefetch ring of x rows (clamped)
        float4 r[RING];
#pragma unroll
        for (int d = 0; d < RING; ++d) {
            int row = max(base + dir * min(d, cl), 0);
            r[d] = *(const float4*)(p + (size_t)row * L);
        }

        for (int k0 = 0; k0 < kMaxPad; k0 += RING) {
#pragma unroll
            for (int kk = 0; kk < RING; ++kk) {
                int k = k0 + kk;

                float d0, d1, d2, d3, f0, f1, f2, f3;
                mma16816(d0, d1, d2, d3, A0, A0, A2, A2, b00, b01);
                mma16816(f0, f1, f2, f3, A0, A0, A2, A2, b10, b11);

                float4 xv = r[kk];
                float e0 = ex2f(xv.x * LOG2E), e1 = ex2f(xv.y * LOG2E);
                float e2 = ex2f(xv.z * LOG2E), e3 = ex2f(xv.w * LOG2E);

                // refill ring slot with row k+RING
                {
                    int row = max(base + dir * min(k + RING, cl), 0);
                    r[kk] = *(const float4*)(p + (size_t)row * L);
                }

                u32 n0 = pkbf(d1 * e1, d0 * e0);
                u32 n2 = pkbf(f1 * e3, f0 * e2);

                bool act = k < cnt;
                A0 = act ? n0 : A0;
                A2 = act ? n2 : A2;

                if (kk == RING - 1) {   // exponent-only rescale (every 8 steps)
                    u32 s0 = __shfl_sync(FULL, A0, lane & ~3);
                    int ee = (int)((s0 >> 7) & 0xff) - 127;
                    u32 h = (u32)(127 - ee) << 7;
                    u32 sc = act ? (h | (h << 16)) : 0x3f803f80u;
                    Ms += act ? ee : 0;
                    A0 = mulbf2(A0, sc);
                    A2 = mulbf2(A2, sc);
                }
            }
        }

        if (!isBwd) {
            sFA[slot][lane][0] = A0;
            sFA[slot][lane][1] = A2;
            if (tig == 0) sMf[slot][g] = Ms;
            __syncthreads();
        } else {
            // beta_m = E * q~ : one more (plain) double-MMA
            float d0, d1, d2, d3, f0, f1, f2, f3;
            mma16816(d0, d1, d2, d3, A0, A0, A2, A2, b00, b01);
            mma16816(f0, f1, f2, f3, A0, A0, A2, A2, b10, b11);
            if (len == 1) { d0 = d1 = 1.f; f0 = f1 = 1.f; }

            __syncthreads();

            u32 a0 = sFA[slot][lane][0], a2 = sFA[slot][lane][1];
            float pr = d0 * bflo(a0) + d1 * bfhi(a0)
                     + f0 * bflo(a2) + f1 * bfhi(a2);
            pr += __shfl_xor_sync(FULL, pr, 1);
            pr += __shfl_xor_sync(FULL, pr, 2);
            float z = __logf(pr) + (float)(Ms + sMf[slot][g]) * LN2;
            if (tig == 0) out[b] = z - sScore[slot][g];
        }
    } else {
        // ---------------- emit / transition warps ----------------
        int slot = w - 8;
        int group = Gs[slot];
#pragma unroll 1
        for (int k2 = 0; k2 < 8; ++k2) {
            int bb = g_perm[group * 8 + k2];
            const int*   lb = label + (size_t)bb * T;
            const float* xb = x + (size_t)bb * T * L;
            int ll = length[bb];

            float acc = 0.f;
            for (int t = lane; t < ll; t += 32) {
                int lab = lb[t];
                acc += __ldg(xb + t * L + lab);
                if (t >= 1) acc += sT[lb[t - 1] * L + lab];
            }
            acc += __shfl_xor_sync(FULL, acc, 16);
            acc += __shfl_xor_sync(FULL, acc, 8);
            acc += __shfl_xor_sync(FULL, acc, 4);
            acc += __shfl_xor_sync(FULL, acc, 2);
            acc += __shfl_xor_sync(FULL, acc, 1);
            if (lane == 0) sScore[slot][k2] = acc;
        }
        __syncthreads();
    }
}

extern "C" void kernel_launch(void* const* d_in, const int* in_sizes, int n_in,
                              void* d_out, int out_size) {
    const float* x      = (const float*)d_in[0];
    const float* trans  = (const float*)d_in[1];
    const int*   label  = (const int*)d_in[2];
    const int*   length = (const int*)d_in[3];
    float*       out    = (float*)d_out;

    int B = in_sizes[3];                 // 4096
    int T = in_sizes[2] / B;             // 512

    sort_kernel<<<1, 512>>>(length, B);

    int grid = (B + 31) / 32;            // 32 batches per block, 128 blocks
    crf_kernel<<<grid, 384>>>(x, trans, label, length, out, B, T);
}

// round 16
// speedup vs baseline: 1.5816x; 1.5816x over previous
#include <cuda_runtime.h>

#define FULL 0xffffffffu
typedef unsigned int u32;

constexpr int L = 16;
constexpr int RING = 8;
constexpr float LOG2E = 1.4426950408889634f;
constexpr float LN2   = 0.6931471805599453f;

__device__ __forceinline__ float ex2f(float v) {
    float r; asm("ex2.approx.f32 %0,%1;" : "=f"(r) : "f"(v)); return r;
}
__device__ __forceinline__ u32 pkbf(float hi, float lo) {
    u32 r; asm("cvt.rn.bf16x2.f32 %0,%1,%2;" : "=r"(r) : "f"(hi), "f"(lo)); return r;
}
// ALU-only bf16x2 pack: round-to-nearest (ties up) then take high halves.
// Valid for positive finite inputs (our states/exps are always > 0).
__device__ __forceinline__ u32 pkrnd(float hi, float lo) {
    u32 a = __float_as_uint(lo) + 0x8000u;
    u32 b = __float_as_uint(hi) + 0x8000u;
    u32 r; asm("prmt.b32 %0,%1,%2,0x7632;" : "=r"(r) : "r"(a), "r"(b));
    return r;
}
__device__ __forceinline__ u32 mulbf2(u32 a, u32 b) {
    u32 r; asm("mul.rn.bf16x2 %0,%1,%2;" : "=r"(r) : "r"(a), "r"(b)); return r;
}
__device__ __forceinline__ float bflo(u32 v) { return __uint_as_float(v << 16); }
__device__ __forceinline__ float bfhi(u32 v) { return __uint_as_float(v & 0xffff0000u); }

__device__ __forceinline__ void mma16816(
    float& d0, float& d1, float& d2, float& d3,
    u32 a0, u32 a1, u32 a2, u32 a3, u32 b0, u32 b1)
{
    asm volatile(
        "mma.sync.aligned.m16n8k16.row.col.f32.bf16.bf16.f32 "
        "{%0,%1,%2,%3}, {%4,%5,%6,%7}, {%8,%9}, {%10,%11,%12,%13};"
        : "=f"(d0), "=f"(d1), "=f"(d2), "=f"(d3)
        : "r"(a0), "r"(a1), "r"(a2), "r"(a3), "r"(b0), "r"(b1),
          "f"(0.f), "f"(0.f), "f"(0.f), "f"(0.f));
}

// state permutation on the MMA k/n axes
__host__ __device__ __forceinline__ int sigma(int i) {
    return (i < 8) ? ((i & 1) ? 2 * i - 1 : 2 * i)
                   : ((i & 1) ? 2 * i - 15 : 2 * i - 14);
}

// Grid = 128 blocks x 32 batches. Block = 384 threads = 12 warps:
//  w0-3 : fwd recursion, batch groups 0-3 (8 batches each)
//  w4-7 : bwd recursion, groups 0-3
//  w8-11: emit + transition scores
// SMSP k hosts fwd-grpk + bwd-grpk + 1 emit warp (R13 layout — best known).
// Chain shortened: d packed to bf16x2 via ALU round+PRMT (no F2FP CVT),
// state update via single HMUL2 with e pre-packed off-chain.
__global__ __launch_bounds__(384, 1) void crf_kernel(
    const float* __restrict__ x, const float* __restrict__ trans,
    const int* __restrict__ label, const int* __restrict__ length,
    float* __restrict__ out, int B, int T)
{
    __shared__ float sE[L * L];
    __shared__ float sT[L * L];
    __shared__ u32   sFA[4][32][2];   // fwd final (A0, A2) per lane
    __shared__ int   sMf[4][8];
    __shared__ float sScore[32];

    int tid  = threadIdx.x;
    int lane = tid & 31;
    int w    = tid >> 5;
    int g    = lane >> 2;     // batch row 0..7
    int tig  = lane & 3;

    if (tid < L * L) {
        float tv = trans[tid];
        sT[tid] = tv;
        sE[tid] = tv * LOG2E;
    }
    __syncthreads();

    int blockBase = blockIdx.x * 32;

    if (w < 8) {
        bool isBwd = w >= 4;
        int grp = w & 3;
        int b = blockBase + grp * 8 + g;
        int len = length[b];
        int m = (len - 1) >> 1;
        int cnt  = isBwd ? max(len - 2 - m, 0) : m;
        int base = isBwd ? (len - 2) : 1;
        int dir  = isBwd ? -1 : 1;
        int cl   = max(cnt - 1, 0);

        int kMax = cnt;
#pragma unroll
        for (int o = 4; o <= 16; o <<= 1)
            kMax = max(kMax, __shfl_xor_sync(FULL, kMax, o));
        int kMaxPad = (kMax + RING - 1) & ~(RING - 1);

        // B fragments with sigma on both axes:
        u32 b00, b01, b10, b11;
        {
            int r0 = 4 * tig;
            int cA = sigma(g);
            int cB = sigma(g + 8);
            float e00, e01, e02, e03, e10, e11, e12, e13;
            if (!isBwd) {
                e00 = sE[r0 * L + cA];       e01 = sE[(r0 + 1) * L + cA];
                e02 = sE[(r0 + 2) * L + cA]; e03 = sE[(r0 + 3) * L + cA];
                e10 = sE[r0 * L + cB];       e11 = sE[(r0 + 1) * L + cB];
                e12 = sE[(r0 + 2) * L + cB]; e13 = sE[(r0 + 3) * L + cB];
            } else {
                e00 = sE[cA * L + r0];       e01 = sE[cA * L + r0 + 1];
                e02 = sE[cA * L + r0 + 2];   e03 = sE[cA * L + r0 + 3];
                e10 = sE[cB * L + r0];       e11 = sE[cB * L + r0 + 1];
                e12 = sE[cB * L + r0 + 2];   e13 = sE[cB * L + r0 + 3];
            }
            b00 = pkbf(ex2f(e01), ex2f(e00));
            b01 = pkbf(ex2f(e03), ex2f(e02));
            b10 = pkbf(ex2f(e11), ex2f(e10));
            b11 = pkbf(ex2f(e13), ex2f(e12));
        }

        // thread tig owns states 4*tig..4*tig+3 of batch b (one float4 per row)
        const float* p = x + (size_t)b * T * L + tig * 4;

        // init: s = exp(x at row 0 (fwd) / len-1 (bwd))
        int ir = isBwd ? (len - 1) : 0;
        float4 iv = *(const float4*)(p + (size_t)ir * L);
        u32 A0 = pkbf(ex2f(iv.y * LOG2E), ex2f(iv.x * LOG2E));
        u32 A2 = pkbf(ex2f(iv.w * LOG2E), ex2f(iv.z * LOG2E));
        int Ms = 0;

        // RING-deep prefetch ring of x rows (clamped)
        float4 r[RING];
#pragma unroll
        for (int d = 0; d < RING; ++d) {
            int row = max(base + dir * min(d, cl), 0);
            r[d] = *(const float4*)(p + (size_t)row * L);
        }

        for (int k0 = 0; k0 < kMaxPad; k0 += RING) {
#pragma unroll
            for (int kk = 0; kk < RING; ++kk) {
                int k = k0 + kk;

                float d0, d1, d2, d3, f0, f1, f2, f3;
                mma16816(d0, d1, d2, d3, A0, A0, A2, A2, b00, b01);
                mma16816(f0, f1, f2, f3, A0, A0, A2, A2, b10, b11);

                // exps + pack OFF the serial chain (independent of MMA)
                float4 xv = r[kk];
                float e0 = ex2f(xv.x * LOG2E), e1 = ex2f(xv.y * LOG2E);
                float e2 = ex2f(xv.z * LOG2E), e3 = ex2f(xv.w * LOG2E);
                u32 eP0 = pkrnd(e1, e0);
                u32 eP2 = pkrnd(e3, e2);

                // refill ring slot with row k+RING
                {
                    int row = max(base + dir * min(k + RING, cl), 0);
                    r[kk] = *(const float4*)(p + (size_t)row * L);
                }

                // chain: ALU pack of d (round+PRMT) -> HMUL2 -> SEL
                u32 n0 = mulbf2(pkrnd(d1, d0), eP0);
                u32 n2 = mulbf2(pkrnd(f1, f0), eP2);

                bool act = k < cnt;
                A0 = act ? n0 : A0;
                A2 = act ? n2 : A2;

                if (kk == RING - 1) {   // exponent-only rescale (every 8 steps)
                    u32 s0 = __shfl_sync(FULL, A0, lane & ~3);
                    int ee = (int)((s0 >> 7) & 0xff) - 127;
                    u32 h = (u32)(127 - ee) << 7;
                    u32 sc = act ? (h | (h << 16)) : 0x3f803f80u;
                    Ms += act ? ee : 0;
                    A0 = mulbf2(A0, sc);
                    A2 = mulbf2(A2, sc);
                }
            }
        }

        if (!isBwd) {
            sFA[grp][lane][0] = A0;
            sFA[grp][lane][1] = A2;
            if (tig == 0) sMf[grp][g] = Ms;
            __syncthreads();
        } else {
            // beta_m = E * q~ : one more (plain) double-MMA
            float d0, d1, d2, d3, f0, f1, f2, f3;
            mma16816(d0, d1, d2, d3, A0, A0, A2, A2, b00, b01);
            mma16816(f0, f1, f2, f3, A0, A0, A2, A2, b10, b11);
            if (len == 1) { d0 = d1 = 1.f; f0 = f1 = 1.f; }

            __syncthreads();

            u32 a0 = sFA[grp][lane][0], a2 = sFA[grp][lane][1];
            float pr = d0 * bflo(a0) + d1 * bfhi(a0)
                     + f0 * bflo(a2) + f1 * bfhi(a2);
            pr += __shfl_xor_sync(FULL, pr, 1);
            pr += __shfl_xor_sync(FULL, pr, 2);
            float z = __logf(pr) + (float)(Ms + sMf[grp][g]) * LN2;
            if (tig == 0) out[b] = z - sScore[grp * 8 + g];
        }
    } else {
        // ---------------- emit / transition warps ----------------
        int we = w - 8;
#pragma unroll 1
        for (int k2 = 0; k2 < 8; ++k2) {
            int sl = we * 8 + k2;
            int bb = blockBase + sl;
            const int*   lb = label + (size_t)bb * T;
            const float* xb = x + (size_t)bb * T * L;
            int ll = length[bb];

            float acc = 0.f;
            for (int t = lane; t < ll; t += 32) {
                int lab = lb[t];
                acc += __ldg(xb + t * L + lab);
                if (t >= 1) acc += sT[lb[t - 1] * L + lab];
            }
            acc += __shfl_xor_sync(FULL, acc, 16);
            acc += __shfl_xor_sync(FULL, acc, 8);
            acc += __shfl_xor_sync(FULL, acc, 4);
            acc += __shfl_xor_sync(FULL, acc, 2);
            acc += __shfl_xor_sync(FULL, acc, 1);
            if (lane == 0) sScore[sl] = acc;
        }
        __syncthreads();
    }
}

extern "C" void kernel_launch(void* const* d_in, const int* in_sizes, int n_in,
                              void* d_out, int out_size) {
    const float* x      = (const float*)d_in[0];
    const float* trans  = (const float*)d_in[1];
    const int*   label  = (const int*)d_in[2];
    const int*   length = (const int*)d_in[3];
    float*       out    = (float*)d_out;

    int B = in_sizes[3];                 // 4096
    int T = in_sizes[2] / B;             // 512

    int grid = (B + 31) / 32;            // 32 batches per block, 128 blocks
    crf_kernel<<<grid, 384>>>(x, trans, label, length, out, B, T);
}